// round 1
// baseline (speedup 1.0000x reference)
#include <cuda_runtime.h>

// single_head_local_attention: b=2, c=256, h=w=64, kernel=7, pad=3
// out[b,c,y,x] = sum_k softmax_k( sum_c q*k_shift / sqrt(c) )[k] * v_shift
// Zero padding: OOB neighborhoods contribute logit 0 (participates in softmax),
// matching the reference which softmaxes the zero-padded correlation tensor.

namespace {
constexpr int Bn = 2, Cn = 256, Hn = 64, Wn = 64;
constexpr int KS = 7, KK = 49, Rr = 3;        // kernel, kernel^2, radius
constexpr int TW = 16, TH = 4, NPIX = TW * TH; // 64-pixel tile
constexpr int NG = 4, CPG = Cn / NG;           // 4 channel groups x 64 ch
constexpr int CHI = 2, NITER = CPG / CHI;      // 2 channels/group/iter, 32 iters
constexpr int HROWS = TH + KS - 1;             // 10
constexpr int HCOLS = TW + KS - 1;             // 22
constexpr int HSTR  = 48;                      // bank-conflict-free stride
constexpr int NSLOT = NG * CHI;                // 8 halo tiles per iteration
constexpr int LOADN = NSLOT * HROWS * HCOLS;   // 1760 elements to stage
constexpr int MAXSLOT = (LOADN + 255) / 256;   // 7 per thread
constexpr int HWn = Hn * Wn;                   // 4096
}

__global__ __launch_bounds__(256, 1)
void lattn_kernel(const float* __restrict__ q, const float* __restrict__ kin,
                  const float* __restrict__ vin, float* __restrict__ out)
{
    __shared__ float halo[NSLOT][HROWS * HSTR];   // 15360 B
    __shared__ float cs[NPIX][KK];                // 12544 B, stride 49 (odd)

    const int tid = threadIdx.x;
    const int g   = tid >> 6;          // channel group 0..3
    const int l   = tid & 63;          // pixel lane within tile
    const int tx  = l & 15;
    const int py  = l >> 4;
    const int bb  = blockIdx.z;
    const int tx0 = blockIdx.x * TW;
    const int ty0 = blockIdx.y * TH;
    const int y   = ty0 + py;
    const int x   = tx0 + tx;

    const size_t bofs = (size_t)bb * Cn * HWn;
    const float* qb = q   + bofs;
    const float* kb = kin + bofs;
    const float* vb = vin + bofs;
    float*       ob = out + bofs;

    // ---- precompute cooperative-loader slots (loop-invariant) ----
    int  s_cbase[MAXSLOT], s_dst[MAXSLOT], s_src[MAXSLOT];
    bool s_live[MAXSLOT], s_ok[MAXSLOT];
    #pragma unroll
    for (int s = 0; s < MAXSLOT; s++) {
        int idx = tid + s * 256;
        s_live[s] = idx < LOADN;
        if (!s_live[s]) idx = 0;
        int t   = idx / (HROWS * HCOLS);
        int rem = idx - t * (HROWS * HCOLS);
        int row = rem / HCOLS;
        int col = rem - row * HCOLS;
        s_cbase[s] = (t >> 1) * CPG + (t & 1);           // + it*CHI at use
        s_dst[s]   = t * (HROWS * HSTR) + row * HSTR + col;
        int gy = ty0 - Rr + row;
        int gx = tx0 - Rr + col;
        s_ok[s]  = ((unsigned)gy < (unsigned)Hn) && ((unsigned)gx < (unsigned)Wn);
        s_src[s] = gy * Wn + gx;
    }

    float acc[KK];
    #pragma unroll
    for (int i = 0; i < KK; i++) acc[i] = 0.f;

    // ================= PHASE 1: correlation =================
    for (int it = 0; it < NITER; it++) {
        #pragma unroll
        for (int s = 0; s < MAXSLOT; s++) {
            if (s_live[s]) {
                float val = 0.f;
                if (s_ok[s])
                    val = kb[(size_t)(s_cbase[s] + it * CHI) * HWn + s_src[s]];
                ((float*)halo)[s_dst[s]] = val;
            }
        }
        __syncthreads();
        #pragma unroll
        for (int j = 0; j < CHI; j++) {
            int c = g * CPG + it * CHI + j;
            float qv = qb[(size_t)c * HWn + y * Wn + x];
            const float* hb = &halo[g * CHI + j][py * HSTR + tx];
            #pragma unroll
            for (int dy = 0; dy < KS; dy++)
                #pragma unroll
                for (int dx = 0; dx < KS; dx++)
                    acc[dy * KS + dx] = fmaf(qv, hb[dy * HSTR + dx], acc[dy * KS + dx]);
        }
        __syncthreads();
    }

    // ---- reduce group partials into cs[pixel][49] ----
    for (int g2 = 0; g2 < NG; g2++) {
        if (g == g2) {
            if (g2 == 0) {
                #pragma unroll
                for (int kk = 0; kk < KK; kk++) cs[l][kk] = acc[kk];
            } else {
                #pragma unroll
                for (int kk = 0; kk < KK; kk++) cs[l][kk] += acc[kk];
            }
        }
        __syncthreads();
    }

    // ---- softmax over 49 offsets, one thread per pixel ----
    if (tid < NPIX) {
        float tv[KK];
        float m = -1e30f;
        #pragma unroll
        for (int kk = 0; kk < KK; kk++) {
            float z = cs[tid][kk] * 0.0625f;   // 1/sqrt(256), temperature=1
            tv[kk] = z;
            m = fmaxf(m, z);
        }
        float ssum = 0.f;
        #pragma unroll
        for (int kk = 0; kk < KK; kk++) {
            float e = __expf(tv[kk] - m);
            tv[kk] = e;
            ssum += e;
        }
        float inv = 1.f / ssum;
        #pragma unroll
        for (int kk = 0; kk < KK; kk++) cs[tid][kk] = tv[kk] * inv;
    }
    __syncthreads();

    // every thread caches its pixel's attention weights in registers
    #pragma unroll
    for (int kk = 0; kk < KK; kk++) acc[kk] = cs[l][kk];

    // ================= PHASE 2: attn . V =================
    for (int it = 0; it < NITER; it++) {
        #pragma unroll
        for (int s = 0; s < MAXSLOT; s++) {
            if (s_live[s]) {
                float val = 0.f;
                if (s_ok[s])
                    val = vb[(size_t)(s_cbase[s] + it * CHI) * HWn + s_src[s]];
                ((float*)halo)[s_dst[s]] = val;
            }
        }
        __syncthreads();
        #pragma unroll
        for (int j = 0; j < CHI; j++) {
            int c = g * CPG + it * CHI + j;
            const float* hb = &halo[g * CHI + j][py * HSTR + tx];
            float o = 0.f;
            #pragma unroll
            for (int dy = 0; dy < KS; dy++)
                #pragma unroll
                for (int dx = 0; dx < KS; dx++)
                    o = fmaf(acc[dy * KS + dx], hb[dy * HSTR + dx], o);
            ob[(size_t)c * HWn + y * Wn + x] = o;
        }
        __syncthreads();
    }
}

extern "C" void kernel_launch(void* const* d_in, const int* in_sizes, int n_in,
                              void* d_out, int out_size)
{
    const float* q = (const float*)d_in[0];
    const float* k = (const float*)d_in[1];
    const float* v = (const float*)d_in[2];
    // d_in[3] = kernel (7), d_in[4] = pad (3): fixed by problem shape.
    float* out = (float*)d_out;

    dim3 grid(Wn / TW, Hn / TH, Bn);   // (4, 16, 2) = 128 blocks
    lattn_kernel<<<grid, 256>>>(q, k, v, out);
}

// round 4
// speedup vs baseline: 1.3093x; 1.3093x over previous
#include <cuda_runtime.h>

// single_head_local_attention: b=2, c=256, h=w=64, kernel=7, pad=3 (shapes fixed).
// out[b,c,y,x] = sum_kk softmax_kk( (1/16) * sum_c q[c,p] * k[c, p+off(kk)] ) * v[c, p+off(kk)]
// Zero padding: OOB logits are 0 and participate in softmax (matches reference).
//
// Design: 8x4 pixel tile per block, 256 threads = 8 channel-groups (1 warp each, 32 ch).
// Within a warp: 16 pixel-pairs x 2 offset-halves (rows dy 0..3 / 3..6; overlap row
// dy=3 masked out of half B). Pixel-pair register blocking -> float2 shared loads,
// 14 FMAs per 4 LDS.64. Halo staged per CHI=2 channels with register-prefetch pipeline.

namespace {
constexpr int Cn = 256, Hn = 64, Wn = 64, HWn = Hn * Wn;
constexpr int KS = 7, KK = 49, Rr = 3;
constexpr int TW = 8, TH = 4, NPIX = TW * TH;      // 32 pixels / block
constexpr int NG = 8, CPG = Cn / NG;               // 8 groups x 32 channels
constexpr int CHI = 2, NITER = CPG / CHI;          // 16 iterations / phase
constexpr int HROWS = TH + KS - 1;                 // 10
constexpr int HCOLS = TW + KS - 1;                 // 14
constexpr int HSTR = 40;                           // 40 mod 32 == 8 -> conflict-free
constexpr int NSLOT = NG * CHI;                    // 16 halo tiles
constexpr int TILEW = HROWS * HSTR;                // 400 words / tile
constexpr int LOADN = NSLOT * HROWS * HCOLS;       // 2240 staged elements
constexpr int NSL = (LOADN + 255) / 256;           // 9 loader slots / thread
constexpr int TAILN = LOADN - (NSL - 1) * 256;     // 192 live threads in slot 8
}

__global__ __launch_bounds__(256, 2)
void lattn2(const float* __restrict__ qg, const float* __restrict__ kg,
            const float* __restrict__ vg, float* __restrict__ outg)
{
    __shared__ __align__(16) float halo[NSLOT * TILEW];   // 25.6 KB
    __shared__ __align__(16) float cs[NPIX][KK];          // 6.3 KB

    const int tid  = threadIdx.x;
    const int g    = tid >> 5;          // channel group (one warp)
    const int lane = tid & 31;
    const int half = lane >> 4;         // offset half: dy base = half*3
    const int pair = lane & 15;         // pixel pair id
    const int pr   = pair >> 2;         // pixel row 0..3
    const int pc2  = (pair & 3) << 1;   // pixel col 0,2,4,6
    const int l0   = pr * TW + pc2;     // left pixel linear id

    const int tx0 = blockIdx.x * TW, ty0 = blockIdx.y * TH;
    const size_t bofs = (size_t)blockIdx.z * Cn * HWn;
    const float* qb = qg + bofs;
    const float* kb = kg + bofs;
    const float* vb = vg + bofs;
    float*       ob = outg + bofs;

    // ---- loader slot geometry: dst packed with channel base, src (-1 = OOB) ----
    int sdst[NSL], ssrc[NSL];
    #pragma unroll
    for (int s = 0; s < NSL; s++) {
        int idx = tid + s * 256;
        if (idx >= LOADN) idx = 0;                     // tail threads masked at use
        int t   = idx / (HROWS * HCOLS);
        int rem = idx - t * (HROWS * HCOLS);
        int row = rem / HCOLS;
        int col = rem - row * HCOLS;
        int cbase = (t >> 1) * CPG + (t & 1);          // channel for it=0
        sdst[s] = (t * TILEW + row * HSTR + col) | (cbase << 16);
        int gy = ty0 - Rr + row, gx = tx0 - Rr + col;
        ssrc[s] = (((unsigned)gy < (unsigned)Hn) && ((unsigned)gx < (unsigned)Wn))
                    ? gy * Wn + gx : -1;
    }
    const bool tail = (tid < TAILN);

    float a0[28], a1[28];
    #pragma unroll
    for (int i = 0; i < 28; i++) { a0[i] = 0.f; a1[i] = 0.f; }

    const int hbase0 = (pr + half * 3) * HSTR + pc2;
    float vals[NSL];

    // =================== PHASE 1: correlation ===================
    #pragma unroll
    for (int s = 0; s < NSL; s++) {
        bool live = (s < NSL - 1) || tail;
        int c = sdst[s] >> 16;
        vals[s] = (live && ssrc[s] >= 0) ? __ldg(kb + (size_t)c * HWn + ssrc[s]) : 0.f;
    }
    for (int it = 0; it < NITER; it++) {
        __syncthreads();                               // buffer free
        #pragma unroll
        for (int s = 0; s < NSL; s++)
            if (s < NSL - 1 || tail) halo[sdst[s] & 0xFFFF] = vals[s];
        __syncthreads();                               // buffer ready
        if (it + 1 < NITER) {
            #pragma unroll
            for (int s = 0; s < NSL; s++) {
                bool live = (s < NSL - 1) || tail;
                int c = (sdst[s] >> 16) + (it + 1) * CHI;
                vals[s] = (live && ssrc[s] >= 0) ? __ldg(kb + (size_t)c * HWn + ssrc[s]) : 0.f;
            }
        }
        #pragma unroll
        for (int j = 0; j < CHI; j++) {
            int c = g * CPG + it * CHI + j;
            float2 qv = *(const float2*)(qb + (size_t)c * HWn + (ty0 + pr) * Wn + tx0 + pc2);
            const float* hb = &halo[(g * CHI + j) * TILEW + hbase0];
            #pragma unroll
            for (int r = 0; r < 4; r++) {
                float2 h0 = *(const float2*)(hb + r * HSTR);
                float2 h1 = *(const float2*)(hb + r * HSTR + 2);
                float2 h2 = *(const float2*)(hb + r * HSTR + 4);
                float2 h3 = *(const float2*)(hb + r * HSTR + 6);
                float f[8] = {h0.x, h0.y, h1.x, h1.y, h2.x, h2.y, h3.x, h3.y};
                #pragma unroll
                for (int dx = 0; dx < 7; dx++) {
                    a0[r * 7 + dx] = fmaf(qv.x, f[dx],     a0[r * 7 + dx]);
                    a1[r * 7 + dx] = fmaf(qv.y, f[dx + 1], a1[r * 7 + dx]);
                }
            }
        }
    }

    // ---- cross-group reduction into cs[pixel][49] via shared atomics ----
    for (int i = tid; i < NPIX * KK; i += 256) ((float*)cs)[i] = 0.f;
    __syncthreads();
    #pragma unroll
    for (int r = 0; r < 4; r++) {
        if (half == 0 || r > 0) {                      // half B skips dy=3 (r=0)
            #pragma unroll
            for (int dx = 0; dx < 7; dx++) {
                int kk = (half * 3 + r) * 7 + dx;
                atomicAdd(&cs[l0][kk],     a0[r * 7 + dx]);
                atomicAdd(&cs[l0 + 1][kk], a1[r * 7 + dx]);
            }
        }
    }
    __syncthreads();

    // ---- softmax over 49 offsets (one thread per pixel; logits = corr/16) ----
    if (tid < NPIX) {
        float m = -1e30f;
        #pragma unroll
        for (int kk = 0; kk < KK; kk++) m = fmaxf(m, cs[tid][kk]);
        m *= 0.0625f;
        float ssum = 0.f;
        #pragma unroll
        for (int kk = 0; kk < KK; kk++) {
            float e = __expf(fmaf(cs[tid][kk], 0.0625f, -m));
            cs[tid][kk] = e;
            ssum += e;
        }
        float inv = 1.f / ssum;
        #pragma unroll
        for (int kk = 0; kk < KK; kk++) cs[tid][kk] *= inv;
    }
    __syncthreads();

    // ---- load attention weights into registers (reuse a0/a1) ----
    #pragma unroll
    for (int r = 0; r < 4; r++) {
        bool use = (half == 0) || (r > 0);
        #pragma unroll
        for (int dx = 0; dx < 7; dx++) {
            int kk = (half * 3 + r) * 7 + dx;
            a0[r * 7 + dx] = use ? cs[l0][kk]     : 0.f;
            a1[r * 7 + dx] = use ? cs[l0 + 1][kk] : 0.f;
        }
    }

    // =================== PHASE 2: attn . V ===================
    #pragma unroll
    for (int s = 0; s < NSL; s++) {
        bool live = (s < NSL - 1) || tail;
        int c = sdst[s] >> 16;
        vals[s] = (live && ssrc[s] >= 0) ? __ldg(vb + (size_t)c * HWn + ssrc[s]) : 0.f;
    }
    for (int it = 0; it < NITER; it++) {
        __syncthreads();
        #pragma unroll
        for (int s = 0; s < NSL; s++)
            if (s < NSL - 1 || tail) halo[sdst[s] & 0xFFFF] = vals[s];
        __syncthreads();
        if (it + 1 < NITER) {
            #pragma unroll
            for (int s = 0; s < NSL; s++) {
                bool live = (s < NSL - 1) || tail;
                int c = (sdst[s] >> 16) + (it + 1) * CHI;
                vals[s] = (live && ssrc[s] >= 0) ? __ldg(vb + (size_t)c * HWn + ssrc[s]) : 0.f;
            }
        }
        #pragma unroll
        for (int j = 0; j < CHI; j++) {
            int c = g * CPG + it * CHI + j;
            const float* hb = &halo[(g * CHI + j) * TILEW + hbase0];
            float o0 = 0.f, o1 = 0.f;
            #pragma unroll
            for (int r = 0; r < 4; r++) {
                float2 h0 = *(const float2*)(hb + r * HSTR);
                float2 h1 = *(const float2*)(hb + r * HSTR + 2);
                float2 h2 = *(const float2*)(hb + r * HSTR + 4);
                float2 h3 = *(const float2*)(hb + r * HSTR + 6);
                float f[8] = {h0.x, h0.y, h1.x, h1.y, h2.x, h2.y, h3.x, h3.y};
                #pragma unroll
                for (int dx = 0; dx < 7; dx++) {
                    o0 = fmaf(a0[r * 7 + dx], f[dx],     o0);
                    o1 = fmaf(a1[r * 7 + dx], f[dx + 1], o1);
                }
            }
            o0 += __shfl_xor_sync(0xFFFFFFFFu, o0, 16);   // combine offset halves
            o1 += __shfl_xor_sync(0xFFFFFFFFu, o1, 16);
            if (half == 0) {
                float2 ov; ov.x = o0; ov.y = o1;
                *(float2*)(ob + (size_t)c * HWn + (ty0 + pr) * Wn + tx0 + pc2) = ov;
            }
        }
    }
}

extern "C" void kernel_launch(void* const* d_in, const int* in_sizes, int n_in,
                              void* d_out, int out_size)
{
    const float* q = (const float*)d_in[0];
    const float* k = (const float*)d_in[1];
    const float* v = (const float*)d_in[2];
    float* out = (float*)d_out;

    dim3 grid(Wn / TW, Hn / TH, 2);   // (8, 16, 2) = 256 blocks
    lattn2<<<grid, 256>>>(q, k, v, out);
}

// round 5
// speedup vs baseline: 1.3835x; 1.0566x over previous
#include <cuda_runtime.h>

// single_head_local_attention: b=2, c=256, h=w=64, kernel=7, pad=3 (shapes fixed).
// out[b,c,y,x] = sum_kk softmax_kk( (1/16) * sum_c q[c,p] * k[c, p+off(kk)] ) * v[c, p+off(kk)]
// Zero padding: OOB logits are 0 and participate in softmax (matches reference).
//
// 8x4 pixel tile / block, 256 threads = 8 channel-groups (1 warp, 32 ch each).
// Warp: 16 pixel-pairs x 2 offset-halves (dy rows 0..3 / 3..6, overlap row masked).
// Double-buffered halo staging: STS overlaps compute, 1 barrier per iteration.

namespace {
constexpr int Cn = 256, Hn = 64, Wn = 64, HWn = Hn * Wn;
constexpr int KS = 7, KK = 49, Rr = 3;
constexpr int TW = 8, TH = 4, NPIX = TW * TH;      // 32 pixels / block
constexpr int NG = 8, CPG = Cn / NG;               // 8 groups x 32 channels
constexpr int CHI = 2, NITER = CPG / CHI;          // 16 iterations / phase
constexpr int HROWS = TH + KS - 1;                 // 10
constexpr int HCOLS = TW + KS - 1;                 // 14
constexpr int HSTR = 24;                           // conflict-free per half-warp phase
constexpr int NSLOT = NG * CHI;                    // 16 halo tiles / buffer
constexpr int TILEW = HROWS * HSTR;                // 240 words / tile
constexpr int BUFW  = NSLOT * TILEW;               // 3840 words / buffer
constexpr int LOADN = NSLOT * HROWS * HCOLS;       // 2240 staged elements
constexpr int NSL = (LOADN + 255) / 256;           // 9 loader slots / thread
constexpr int TAILN = LOADN - (NSL - 1) * 256;     // 192 live threads in last slot
}

__global__ __launch_bounds__(256, 2)
void lattn3(const float* __restrict__ qg, const float* __restrict__ kg,
            const float* __restrict__ vg, float* __restrict__ outg)
{
    __shared__ __align__(16) float halo[2 * BUFW];        // 30.7 KB (double buffer)
    __shared__ __align__(16) float cs[NPIX][KK];          // 6.3 KB

    const int tid  = threadIdx.x;
    const int g    = tid >> 5;          // channel group (one warp)
    const int lane = tid & 31;
    const int half = lane >> 4;         // offset half: dy base = half*3
    const int pair = lane & 15;         // pixel pair id
    const int pr   = pair >> 2;         // pixel row 0..3
    const int pc2  = (pair & 3) << 1;   // pixel col 0,2,4,6
    const int l0   = pr * TW + pc2;     // left pixel linear id

    const int tx0 = blockIdx.x * TW, ty0 = blockIdx.y * TH;
    const size_t bofs = (size_t)blockIdx.z * Cn * HWn;
    const float* qb = qg + bofs;
    const float* kb = kg + bofs;
    const float* vb = vg + bofs;
    float*       ob = outg + bofs;

    // cs zero-init (read only after phase-1 barriers)
    for (int i = tid; i < NPIX * KK; i += 256) ((float*)cs)[i] = 0.f;

    // ---- loader slot geometry: dst packed with channel base, src (-1 = OOB) ----
    int sdst[NSL], ssrc[NSL];
    #pragma unroll
    for (int s = 0; s < NSL; s++) {
        int idx = tid + s * 256;
        if (idx >= LOADN) idx = 0;                     // tail threads masked at use
        int t   = idx / (HROWS * HCOLS);
        int rem = idx - t * (HROWS * HCOLS);
        int row = rem / HCOLS;
        int col = rem - row * HCOLS;
        int cbase = (t >> 1) * CPG + (t & 1);          // channel for it=0
        sdst[s] = (t * TILEW + row * HSTR + col) | (cbase << 16);
        int gy = ty0 - Rr + row, gx = tx0 - Rr + col;
        ssrc[s] = (((unsigned)gy < (unsigned)Hn) && ((unsigned)gx < (unsigned)Wn))
                    ? gy * Wn + gx : -1;
    }
    const bool tail = (tid < TAILN);

    float a0[28], a1[28];
    #pragma unroll
    for (int i = 0; i < 28; i++) { a0[i] = 0.f; a1[i] = 0.f; }

    const int hbase0 = (pr + half * 3) * HSTR + pc2;
    float vals[NSL];

    // =================== PHASE 1: correlation ===================
    #pragma unroll
    for (int s = 0; s < NSL; s++) {                       // pair 0
        bool live = (s < NSL - 1) || tail;
        int c = sdst[s] >> 16;
        vals[s] = (live && ssrc[s] >= 0) ? __ldg(kb + (size_t)c * HWn + ssrc[s]) : 0.f;
    }
    #pragma unroll
    for (int s = 0; s < NSL; s++)                         // store buf0
        if (s < NSL - 1 || tail) halo[sdst[s] & 0xFFFF] = vals[s];
    #pragma unroll
    for (int s = 0; s < NSL; s++) {                       // pair 1
        bool live = (s < NSL - 1) || tail;
        int c = (sdst[s] >> 16) + CHI;
        vals[s] = (live && ssrc[s] >= 0) ? __ldg(kb + (size_t)c * HWn + ssrc[s]) : 0.f;
    }
    __syncthreads();

    for (int it = 0; it < NITER; it++) {
        if (it + 1 < NITER) {
            int bo = ((it + 1) & 1) * BUFW;
            #pragma unroll
            for (int s = 0; s < NSL; s++)
                if (s < NSL - 1 || tail) halo[(sdst[s] & 0xFFFF) + bo] = vals[s];
        }
        if (it + 2 < NITER) {
            #pragma unroll
            for (int s = 0; s < NSL; s++) {
                bool live = (s < NSL - 1) || tail;
                int c = (sdst[s] >> 16) + (it + 2) * CHI;
                vals[s] = (live && ssrc[s] >= 0) ? __ldg(kb + (size_t)c * HWn + ssrc[s]) : 0.f;
            }
        }
        const float* hbb = &halo[(it & 1) * BUFW + hbase0];
        #pragma unroll
        for (int j = 0; j < CHI; j++) {
            int c = g * CPG + it * CHI + j;
            float2 qv = *(const float2*)(qb + (size_t)c * HWn + (ty0 + pr) * Wn + tx0 + pc2);
            const float* hb = hbb + (g * CHI + j) * TILEW;
            #pragma unroll
            for (int r = 0; r < 4; r++) {
                float2 h0 = *(const float2*)(hb + r * HSTR);
                float2 h1 = *(const float2*)(hb + r * HSTR + 2);
                float2 h2 = *(const float2*)(hb + r * HSTR + 4);
                float2 h3 = *(const float2*)(hb + r * HSTR + 6);
                float f[8] = {h0.x, h0.y, h1.x, h1.y, h2.x, h2.y, h3.x, h3.y};
                #pragma unroll
                for (int dx = 0; dx < 7; dx++) {
                    a0[r * 7 + dx] = fmaf(qv.x, f[dx],     a0[r * 7 + dx]);
                    a1[r * 7 + dx] = fmaf(qv.y, f[dx + 1], a1[r * 7 + dx]);
                }
            }
        }
        __syncthreads();
    }

    // ---- cross-group reduction into cs[pixel][49] via shared atomics ----
    #pragma unroll
    for (int r = 0; r < 4; r++) {
        if (half == 0 || r > 0) {                      // half B skips dy=3 (r=0)
            #pragma unroll
            for (int dx = 0; dx < 7; dx++) {
                int kk = (half * 3 + r) * 7 + dx;
                atomicAdd(&cs[l0][kk],     a0[r * 7 + dx]);
                atomicAdd(&cs[l0 + 1][kk], a1[r * 7 + dx]);
            }
        }
    }
    __syncthreads();

    // ---- softmax over 49 offsets (one thread per pixel; logits = corr/16) ----
    if (tid < NPIX) {
        float m = -1e30f;
        #pragma unroll
        for (int kk = 0; kk < KK; kk++) m = fmaxf(m, cs[tid][kk]);
        m *= 0.0625f;
        float ssum = 0.f;
        #pragma unroll
        for (int kk = 0; kk < KK; kk++) {
            float e = __expf(fmaf(cs[tid][kk], 0.0625f, -m));
            cs[tid][kk] = e;
            ssum += e;
        }
        float inv = 1.f / ssum;
        #pragma unroll
        for (int kk = 0; kk < KK; kk++) cs[tid][kk] *= inv;
    }
    __syncthreads();

    // ---- load attention weights into registers (reuse a0/a1) ----
    #pragma unroll
    for (int r = 0; r < 4; r++) {
        bool use = (half == 0) || (r > 0);
        #pragma unroll
        for (int dx = 0; dx < 7; dx++) {
            int kk = (half * 3 + r) * 7 + dx;
            a0[r * 7 + dx] = use ? cs[l0][kk]     : 0.f;
            a1[r * 7 + dx] = use ? cs[l0 + 1][kk] : 0.f;
        }
    }
    __syncthreads();   // weights read; halo reuse below is safe via staging syncs

    // =================== PHASE 2: attn . V ===================
    #pragma unroll
    for (int s = 0; s < NSL; s++) {
        bool live = (s < NSL - 1) || tail;
        int c = sdst[s] >> 16;
        vals[s] = (live && ssrc[s] >= 0) ? __ldg(vb + (size_t)c * HWn + ssrc[s]) : 0.f;
    }
    #pragma unroll
    for (int s = 0; s < NSL; s++)
        if (s < NSL - 1 || tail) halo[sdst[s] & 0xFFFF] = vals[s];
    #pragma unroll
    for (int s = 0; s < NSL; s++) {
        bool live = (s < NSL - 1) || tail;
        int c = (sdst[s] >> 16) + CHI;
        vals[s] = (live && ssrc[s] >= 0) ? __ldg(vb + (size_t)c * HWn + ssrc[s]) : 0.f;
    }
    __syncthreads();

    for (int it = 0; it < NITER; it++) {
        if (it + 1 < NITER) {
            int bo = ((it + 1) & 1) * BUFW;
            #pragma unroll
            for (int s = 0; s < NSL; s++)
                if (s < NSL - 1 || tail) halo[(sdst[s] & 0xFFFF) + bo] = vals[s];
        }
        if (it + 2 < NITER) {
            #pragma unroll
            for (int s = 0; s < NSL; s++) {
                bool live = (s < NSL - 1) || tail;
                int c = (sdst[s] >> 16) + (it + 2) * CHI;
                vals[s] = (live && ssrc[s] >= 0) ? __ldg(vb + (size_t)c * HWn + ssrc[s]) : 0.f;
            }
        }
        const float* hbb = &halo[(it & 1) * BUFW + hbase0];
        #pragma unroll
        for (int j = 0; j < CHI; j++) {
            int c = g * CPG + it * CHI + j;
            const float* hb = hbb + (g * CHI + j) * TILEW;
            float o0 = 0.f, o1 = 0.f;
            #pragma unroll
            for (int r = 0; r < 4; r++) {
                float2 h0 = *(const float2*)(hb + r * HSTR);
                float2 h1 = *(const float2*)(hb + r * HSTR + 2);
                float2 h2 = *(const float2*)(hb + r * HSTR + 4);
                float2 h3 = *(const float2*)(hb + r * HSTR + 6);
                float f[8] = {h0.x, h0.y, h1.x, h1.y, h2.x, h2.y, h3.x, h3.y};
                #pragma unroll
                for (int dx = 0; dx < 7; dx++) {
                    o0 = fmaf(a0[r * 7 + dx], f[dx],     o0);
                    o1 = fmaf(a1[r * 7 + dx], f[dx + 1], o1);
                }
            }
            o0 += __shfl_xor_sync(0xFFFFFFFFu, o0, 16);   // combine offset halves
            o1 += __shfl_xor_sync(0xFFFFFFFFu, o1, 16);
            if (half == 0) {
                float2 ov; ov.x = o0; ov.y = o1;
                *(float2*)(ob + (size_t)c * HWn + (ty0 + pr) * Wn + tx0 + pc2) = ov;
            }
        }
        __syncthreads();
    }
}

extern "C" void kernel_launch(void* const* d_in, const int* in_sizes, int n_in,
                              void* d_out, int out_size)
{
    const float* q = (const float*)d_in[0];
    const float* k = (const float*)d_in[1];
    const float* v = (const float*)d_in[2];
    float* out = (float*)d_out;

    dim3 grid(Wn / TW, Hn / TH, 2);   // (8, 16, 2) = 256 blocks
    lattn3<<<grid, 256>>>(q, k, v, out);
}